// round 5
// baseline (speedup 1.0000x reference)
#include <cuda_runtime.h>
#include <math.h>

// Problem constants
#define TOK   8192      // B*S
#define DD    2048      // D
#define NE    64        // experts
#define KSPL  24        // K-split (1536 CTAs, ~5.3 chunks each)
#define NCHUNK 128      // 2048/16 chunks of d
#define BM    128       // tokens per CTA
#define BK    16        // d per chunk
#define NPROB 16384     // TOK * TOPK
#define ROWPAD 132      // padded A row (floats)

// Partial scores scratch: [KSPL][TOK][NE] = 50.3 MB (fits L2)
__device__ float g_part[KSPL * TOK * NE];

typedef unsigned long long u64;

__device__ __forceinline__ u64 ffma2(u64 a, u64 b, u64 c) {
    u64 d;
    asm("fma.rn.f32x2 %0, %1, %2, %3;" : "=l"(d) : "l"(a), "l"(b), "l"(c));
    return d;
}
__device__ __forceinline__ u64 dup2(float x) {
    u64 d;
    asm("mov.b64 %0, {%1, %1};" : "=l"(d) : "f"(x));
    return d;
}
__device__ __forceinline__ void lds_pair64(u64& a, u64& b, unsigned saddr) {
    asm volatile("ld.shared.v2.b64 {%0, %1}, [%2];" : "=l"(a), "=l"(b) : "r"(saddr));
}
__device__ __forceinline__ void lds_f4(float& x, float& y, float& z, float& w, unsigned saddr) {
    asm volatile("ld.shared.v4.f32 {%0, %1, %2, %3}, [%4];"
                 : "=f"(x), "=f"(y), "=f"(z), "=f"(w) : "r"(saddr));
}

__global__ __launch_bounds__(256, 3)
void gemm_amp_phase_kernel(const float* __restrict__ xr,
                           const float* __restrict__ xi,
                           const float* __restrict__ W) {
    // A transposed [k][token] (pad to 132), W [k][expert]
    __shared__ float sAa[BK][ROWPAD];
    __shared__ float sAp[BK][ROWPAD];
    __shared__ float sWa[BK][NE];
    __shared__ float sWp[BK][NE];

    const int tok0 = blockIdx.x * BM;
    const int ks   = blockIdx.y;
    const int tid  = threadIdx.x;
    const int my   = tid & 31;     // m-group: tokens my*4 .. my*4+3
    const int nx   = tid >> 5;     // n-group: experts nx*8 .. nx*8+7 (warp-uniform)
    const int m0   = my * 4;
    const int n0   = nx * 8;

    // acc[m][npair] packed f32x2 along n (experts n0+2j, n0+2j+1)
    u64 acc[4][4];
#pragma unroll
    for (int m = 0; m < 4; m++)
#pragma unroll
        for (int j = 0; j < 4; j++) acc[m][j] = 0ull;

    // chunk range: 128 chunks over 24 splits (first 8 get 6, rest 5)
    const int base = ks * (NCHUNK / KSPL) + (ks < (NCHUNK % KSPL) ? ks : (NCHUNK % KSPL));
    const int cnt  = NCHUNK / KSPL + (ks < (NCHUNK % KSPL) ? 1 : 0);

    const unsigned sAa_b = (unsigned)__cvta_generic_to_shared(&sAa[0][0]);
    const unsigned sAp_b = (unsigned)__cvta_generic_to_shared(&sAp[0][0]);
    const unsigned sWa_b = (unsigned)__cvta_generic_to_shared(&sWa[0][0]);
    const unsigned sWp_b = (unsigned)__cvta_generic_to_shared(&sWp[0][0]);

    for (int c = base; c < base + cnt; c++) {
        const int dc = c * BK;
        // ---- W chunk: rows [dc,dc+16) amp / [2048+dc,..) phase (256 f4 each)
        {
            const int row = tid >> 4;          // 0..15
            const int col = (tid & 15) << 2;   // 0..60
            *(float4*)&sWa[row][col] = *(const float4*)&W[(size_t)(dc + row) * NE + col];
            *(float4*)&sWp[row][col] = *(const float4*)&W[(size_t)(DD + dc + row) * NE + col];
        }
        // ---- x load + amp/phase, store transposed [k][token]
#pragma unroll
        for (int r = 0; r < 2; r++) {
            const int v    = tid + 256 * r;   // 0..511
            const int t    = v >> 2;          // token 0..127
            const int dcol = (v & 3) << 2;    // 0,4,8,12
            const size_t gbase = (size_t)(tok0 + t) * DD + dc + dcol;
            const float4 a = *(const float4*)&xr[gbase];
            const float4 b = *(const float4*)&xi[gbase];
            float am[4], ph[4];
            am[0] = sqrtf(fmaf(a.x, a.x, b.x * b.x)); ph[0] = atan2f(b.x, a.x);
            am[1] = sqrtf(fmaf(a.y, a.y, b.y * b.y)); ph[1] = atan2f(b.y, a.y);
            am[2] = sqrtf(fmaf(a.z, a.z, b.z * b.z)); ph[2] = atan2f(b.z, a.z);
            am[3] = sqrtf(fmaf(a.w, a.w, b.w * b.w)); ph[3] = atan2f(b.w, a.w);
#pragma unroll
            for (int u = 0; u < 4; u++) {
                sAa[dcol + u][t] = am[u];
                sAp[dcol + u][t] = ph[u];
            }
        }
        __syncthreads();

        // ---- MMA: 16 k-steps, 4m x 8n, f32x2 pairs along n
#pragma unroll
        for (int kk = 0; kk < BK; kk++) {
            // A: 16 B contiguous per lane, conflict-free across warp
            float aa0, aa1, aa2, aa3, ap0, ap1, ap2, ap3;
            const unsigned aoff = (unsigned)((kk * ROWPAD + m0) * 4);
            lds_f4(aa0, aa1, aa2, aa3, sAa_b + aoff);
            lds_f4(ap0, ap1, ap2, ap3, sAp_b + aoff);
            // W: packed n-pairs, warp-uniform broadcast
            u64 wa[4], wp[4];
            const unsigned woff = (unsigned)((kk * NE + n0) * 4);
            lds_pair64(wa[0], wa[1], sWa_b + woff);
            lds_pair64(wa[2], wa[3], sWa_b + woff + 16);
            lds_pair64(wp[0], wp[1], sWp_b + woff);
            lds_pair64(wp[2], wp[3], sWp_b + woff + 16);

            const float aav[4] = {aa0, aa1, aa2, aa3};
            const float apv[4] = {ap0, ap1, ap2, ap3};
#pragma unroll
            for (int m = 0; m < 4; m++) {
                const u64 ad = dup2(aav[m]);
                const u64 pd = dup2(apv[m]);
#pragma unroll
                for (int j = 0; j < 4; j++) {
                    acc[m][j] = ffma2(ad, wa[j], ffma2(pd, wp[j], acc[m][j]));
                }
            }
        }
        __syncthreads();
    }

    // ---- write partials: n-packed accs store directly (16 B per pair-of-pairs)
    float* dst = g_part + ((size_t)ks * TOK + tok0) * NE;
#pragma unroll
    for (int m = 0; m < 4; m++) {
        const size_t row = (size_t)(m0 + m) * NE + n0;
        ulonglong2 v0; v0.x = acc[m][0]; v0.y = acc[m][1];
        ulonglong2 v1; v1.x = acc[m][2]; v1.y = acc[m][3];
        *(ulonglong2*)&dst[row]     = v0;
        *(ulonglong2*)&dst[row + 4] = v1;
    }
}

__global__ __launch_bounds__(256)
void topk_kernel(const float* __restrict__ bvec, float* __restrict__ out) {
    const int gtid = blockIdx.x * blockDim.x + threadIdx.x;
    const int tok  = gtid >> 5;
    const int lane = threadIdx.x & 31;
    if (tok >= TOK) return;

    // each lane owns experts 2*lane, 2*lane+1; sum KSPL partials
    float s0 = 0.0f, s1 = 0.0f;
#pragma unroll
    for (int ks = 0; ks < KSPL; ks++) {
        const float2 v = *(const float2*)&g_part[((size_t)ks * TOK + tok) * NE + lane * 2];
        s0 += v.x; s1 += v.y;
    }
    s0 += bvec[2 * lane];
    s1 += bvec[2 * lane + 1];

    // top-1, jax tie-break (lower index wins on equal)
    float bv; int bi;
    if (s1 > s0) { bv = s1; bi = 2 * lane + 1; } else { bv = s0; bi = 2 * lane; }
#pragma unroll
    for (int off = 16; off > 0; off >>= 1) {
        const float ov = __shfl_down_sync(0xffffffffu, bv, off);
        const int   oi = __shfl_down_sync(0xffffffffu, bi, off);
        if (ov > bv || (ov == bv && oi < bi)) { bv = ov; bi = oi; }
    }
    bv = __shfl_sync(0xffffffffu, bv, 0);
    bi = __shfl_sync(0xffffffffu, bi, 0);

    // top-2: exclude bi
    const float NEG = -3.4e38f;
    float t0 = (2 * lane     == bi) ? NEG : s0;
    float t1 = (2 * lane + 1 == bi) ? NEG : s1;
    float cv; int ci;
    if (t1 > t0) { cv = t1; ci = 2 * lane + 1; } else { cv = t0; ci = 2 * lane; }
#pragma unroll
    for (int off = 16; off > 0; off >>= 1) {
        const float ov = __shfl_down_sync(0xffffffffu, cv, off);
        const int   oi = __shfl_down_sync(0xffffffffu, ci, off);
        if (ov > cv || (ov == cv && oi < ci)) { cv = ov; ci = oi; }
    }

    if (lane == 0) {
        // renormalized top-2 softmax: global denominator cancels, max = bv
        const float r  = expf(cv - bv);
        const float dn = 1.0f + r;
        out[tok * 2]             = 1.0f / dn;
        out[tok * 2 + 1]         = r / dn;
        out[NPROB + tok * 2]     = (float)bi;
        out[NPROB + tok * 2 + 1] = (float)ci;
    }
}

extern "C" void kernel_launch(void* const* d_in, const int* in_sizes, int n_in,
                              void* d_out, int out_size) {
    const float* xr = (const float*)d_in[0];   // x_real [4,2048,2048]
    const float* xi = (const float*)d_in[1];   // x_imag [4,2048,2048]
    const float* W  = (const float*)d_in[2];   // [4096, 64]
    const float* b  = (const float*)d_in[3];   // [64]
    float* out = (float*)d_out;                // [16384 probs][16384 indices]

    dim3 grid1(TOK / BM, KSPL);
    gemm_amp_phase_kernel<<<grid1, 256>>>(xr, xi, W);
    topk_kernel<<<TOK * 32 / 256, 256>>>(b, out);
}

// round 8
// speedup vs baseline: 1.1059x; 1.1059x over previous
#include <cuda_runtime.h>
#include <cuda_bf16.h>
#include <math.h>
#include <stdint.h>

// ---------------- problem constants ----------------
#define TOK    8192
#define DD     2048
#define NE     64
#define KSPL   4          // K-split -> grid (64, 4)
#define DSPL   512        // d per split
#define BM     128        // tokens per CTA
#define CHUNK  64         // k per chunk
#define NCHK   (DSPL / CHUNK)   // 8 chunks
#define NPROB  16384

// partial scores [KSPL][TOK][NE] = 8 MB
__device__ float g_part[KSPL * TOK * NE];
// W transposed + 3-level bf16 split: [expert n][feature k 0..4095]
__device__ __nv_bfloat16 g_Wh[NE * 2 * DD];
__device__ __nv_bfloat16 g_Wm[NE * 2 * DD];
__device__ __nv_bfloat16 g_Wl[NE * 2 * DD];

// ---------------- helpers ----------------
__device__ __forceinline__ uint32_t smem_u32(const void* p) {
    uint32_t a;
    asm("{ .reg .u64 t; cvta.to.shared.u64 t, %1; cvt.u32.u64 %0, t; }" : "=r"(a) : "l"(p));
    return a;
}
__device__ __forceinline__ uint32_t packbf(float lo, float hi) {
    __nv_bfloat162 v = __floats2bfloat162_rn(lo, hi);
    return *reinterpret_cast<uint32_t*>(&v);
}
// 3-level split of a float pair into bf16x2 hi / mid / lo
__device__ __forceinline__ void split3(float x, float y,
                                       uint32_t& h, uint32_t& m, uint32_t& l) {
    h = packbf(x, y);
    const float xh = __uint_as_float(h << 16);
    const float yh = __uint_as_float(h & 0xFFFF0000u);
    const float rx = x - xh, ry = y - yh;          // exact
    m = packbf(rx, ry);
    const float xm = __uint_as_float(m << 16);
    const float ym = __uint_as_float(m & 0xFFFF0000u);
    l = packbf(rx - xm, ry - ym);
}
__device__ __forceinline__ void mma16816(float* c, const uint32_t* a, const uint32_t* b) {
    asm volatile(
        "mma.sync.aligned.m16n8k16.row.col.f32.bf16.bf16.f32 "
        "{%0,%1,%2,%3}, {%4,%5,%6,%7}, {%8,%9}, {%0,%1,%2,%3};"
        : "+f"(c[0]), "+f"(c[1]), "+f"(c[2]), "+f"(c[3])
        : "r"(a[0]), "r"(a[1]), "r"(a[2]), "r"(a[3]), "r"(b[0]), "r"(b[1]));
}
__device__ __forceinline__ void ldsm4(uint32_t* r, uint32_t addr) {
    asm volatile("ldmatrix.sync.aligned.m8n8.x4.shared.b16 {%0,%1,%2,%3}, [%4];"
                 : "=r"(r[0]), "=r"(r[1]), "=r"(r[2]), "=r"(r[3]) : "r"(addr));
}
__device__ __forceinline__ void stsh128(uint32_t addr, uint4 v) {
    asm volatile("st.shared.v4.b32 [%0], {%1, %2, %3, %4};"
                 :: "r"(addr), "r"(v.x), "r"(v.y), "r"(v.z), "r"(v.w) : "memory");
}

// ---------------- setup: transpose + 3-level bf16-split W ----------------
__global__ __launch_bounds__(256)
void wsplit_kernel(const float* __restrict__ W) {
    __shared__ float tile[64][65];
    const int k0 = blockIdx.x * 64;
    const int tid = threadIdx.x;
    for (int i = tid; i < 64 * 64; i += 256) {
        const int r = i >> 6, n = i & 63;
        tile[r][n] = W[(size_t)(k0 + r) * NE + n];
    }
    __syncthreads();
    const int n  = tid >> 2;
    const int kb = (tid & 3) * 16;
#pragma unroll
    for (int kk = 0; kk < 16; kk++) {
        const float v = tile[kb + kk][n];
        const __nv_bfloat16 h = __float2bfloat16_rn(v);
        const float r1 = v - __bfloat162float(h);
        const __nv_bfloat16 m = __float2bfloat16_rn(r1);
        const float r2 = r1 - __bfloat162float(m);
        const size_t idx = (size_t)n * (2 * DD) + k0 + kb + kk;
        g_Wh[idx] = h;
        g_Wm[idx] = m;
        g_Wl[idx] = __float2bfloat16_rn(r2);
    }
}

// ---------------- main: fused amp/phase + 3-level split-bf16 mma GEMM ----------------
// 8 warps, each owns m16 (16 tokens) x n64. A frags built in registers.
__global__ __launch_bounds__(256, 2)
void gemm_mma_kernel(const float* __restrict__ xr, const float* __restrict__ xi) {
    // W tiles: 6 arrays [Wa_h, Wa_m, Wa_l, Wp_h, Wp_m, Wp_l], 64n x 64k bf16, swizzled
    __shared__ __align__(128) uint8_t sW[6 * 8192];
    const uint32_t swb = smem_u32(sW);

    const int tid  = threadIdx.x;
    const int w    = tid >> 5;
    const int lane = tid & 31;
    const int qr   = lane >> 2;          // frag row 0..7
    const int qc   = (lane & 3) * 2;     // frag col pair
    const int tok0 = blockIdx.x * BM;
    const int ks   = blockIdx.y;

    // ldmatrix lane-address constants
    const uint32_t ldrow = ((lane >> 4) << 3) + (lane & 7);     // 0..15
    const uint32_t kboff = ((lane >> 3) & 1) * 16;              // 0 / 16 bytes
    const uint32_t kxor  = (lane & 7) << 4;                     // swizzle XOR

    float acc[8][4];
#pragma unroll
    for (int nt = 0; nt < 8; nt++)
#pragma unroll
        for (int j = 0; j < 4; j++) acc[nt][j] = 0.0f;

    const int rA = tok0 + w * 16 + qr;         // token row (and +8)

    for (int c = 0; c < NCHK; c++) {
        const int koff = ks * DSPL + c * CHUNK;
        __syncthreads();
        // ---- stage W: 6 arrays, each thread moves 32B per array (swizzled smem)
        {
            const int n  = tid >> 2;
            const int ke = (tid & 3) * 16;
            const size_t gA = (size_t)n * (2 * DD) + koff + ke;
            const size_t gP = gA + DD;
            const uint32_t row = (uint32_t)n * 128;
            const uint32_t xv  = (uint32_t)(n & 7) << 4;
            const uint32_t c0  = row + (((uint32_t)(ke * 2)) ^ xv);
            const uint32_t c1  = row + (((uint32_t)(ke * 2 + 16)) ^ xv);
            uint4 v;
            v = *(const uint4*)(g_Wh + gA);     stsh128(swb + 0 * 8192 + c0, v);
            v = *(const uint4*)(g_Wh + gA + 8); stsh128(swb + 0 * 8192 + c1, v);
            v = *(const uint4*)(g_Wm + gA);     stsh128(swb + 1 * 8192 + c0, v);
            v = *(const uint4*)(g_Wm + gA + 8); stsh128(swb + 1 * 8192 + c1, v);
            v = *(const uint4*)(g_Wl + gA);     stsh128(swb + 2 * 8192 + c0, v);
            v = *(const uint4*)(g_Wl + gA + 8); stsh128(swb + 2 * 8192 + c1, v);
            v = *(const uint4*)(g_Wh + gP);     stsh128(swb + 3 * 8192 + c0, v);
            v = *(const uint4*)(g_Wh + gP + 8); stsh128(swb + 3 * 8192 + c1, v);
            v = *(const uint4*)(g_Wm + gP);     stsh128(swb + 4 * 8192 + c0, v);
            v = *(const uint4*)(g_Wm + gP + 8); stsh128(swb + 4 * 8192 + c1, v);
            v = *(const uint4*)(g_Wl + gP);     stsh128(swb + 5 * 8192 + c0, v);
            v = *(const uint4*)(g_Wl + gP + 8); stsh128(swb + 5 * 8192 + c1, v);
        }
        __syncthreads();

#pragma unroll
        for (int kt = 0; kt < 4; kt++) {
            const int cc = kt * 16 + qc;     // chunk-local col (even)
            // ---- load x for this thread's A-fragment positions
            const size_t b0 = (size_t)rA * DD + koff + cc;
            const size_t b1 = b0 + (size_t)8 * DD;
            const float2 r00 = *(const float2*)(xr + b0);
            const float2 r02 = *(const float2*)(xr + b0 + 8);
            const float2 r10 = *(const float2*)(xr + b1);
            const float2 r12 = *(const float2*)(xr + b1 + 8);
            const float2 i00 = *(const float2*)(xi + b0);
            const float2 i02 = *(const float2*)(xi + b0 + 8);
            const float2 i10 = *(const float2*)(xi + b1);
            const float2 i12 = *(const float2*)(xi + b1 + 8);

            // ---- amp / phase (8 elems) — same math as the proven fp32 kernels
            const float a00 = sqrtf(fmaf(r00.x, r00.x, i00.x * i00.x)), p00 = atan2f(i00.x, r00.x);
            const float a01 = sqrtf(fmaf(r00.y, r00.y, i00.y * i00.y)), p01 = atan2f(i00.y, r00.y);
            const float a10 = sqrtf(fmaf(r10.x, r10.x, i10.x * i10.x)), p10 = atan2f(i10.x, r10.x);
            const float a11 = sqrtf(fmaf(r10.y, r10.y, i10.y * i10.y)), p11 = atan2f(i10.y, r10.y);
            const float a02 = sqrtf(fmaf(r02.x, r02.x, i02.x * i02.x)), p02 = atan2f(i02.x, r02.x);
            const float a03 = sqrtf(fmaf(r02.y, r02.y, i02.y * i02.y)), p03 = atan2f(i02.y, r02.y);
            const float a12 = sqrtf(fmaf(r12.x, r12.x, i12.x * i12.x)), p12 = atan2f(i12.x, r12.x);
            const float a13 = sqrtf(fmaf(r12.y, r12.y, i12.y * i12.y)), p13 = atan2f(i12.y, r12.y);

            // ---- 3-level bf16 split into A-fragment layout
            uint32_t Ah[4], Am[4], Al[4], Ph[4], Pm[4], Pl[4];
            split3(a00, a01, Ah[0], Am[0], Al[0]);
            split3(a10, a11, Ah[1], Am[1], Al[1]);
            split3(a02, a03, Ah[2], Am[2], Al[2]);
            split3(a12, a13, Ah[3], Am[3], Al[3]);
            split3(p00, p01, Ph[0], Pm[0], Pl[0]);
            split3(p10, p11, Ph[1], Pm[1], Pl[1]);
            split3(p02, p03, Ph[2], Pm[2], Pl[2]);
            split3(p12, p13, Ph[3], Pm[3], Pl[3]);

            const uint32_t kb = ((uint32_t)(kt * 32) + kboff) ^ kxor;
            uint32_t wreg[16];

            // ---- amp side: Wh consumed by Ah,Am,Al; Wm by Ah,Am; Wl by Ah
#pragma unroll
            for (int g = 0; g < 4; g++)
                ldsm4(&wreg[g * 4], swb + 0 * 8192 + (g * 16 + ldrow) * 128 + kb);
#pragma unroll
            for (int nt = 0; nt < 8; nt++) {
                mma16816(acc[nt], Ah, &wreg[nt * 2]);
                mma16816(acc[nt], Am, &wreg[nt * 2]);
                mma16816(acc[nt], Al, &wreg[nt * 2]);
            }
#pragma unroll
            for (int g = 0; g < 4; g++)
                ldsm4(&wreg[g * 4], swb + 1 * 8192 + (g * 16 + ldrow) * 128 + kb);
#pragma unroll
            for (int nt = 0; nt < 8; nt++) {
                mma16816(acc[nt], Ah, &wreg[nt * 2]);
                mma16816(acc[nt], Am, &wreg[nt * 2]);
            }
#pragma unroll
            for (int g = 0; g < 4; g++)
                ldsm4(&wreg[g * 4], swb + 2 * 8192 + (g * 16 + ldrow) * 128 + kb);
#pragma unroll
            for (int nt = 0; nt < 8; nt++)
                mma16816(acc[nt], Ah, &wreg[nt * 2]);

            // ---- phase side
#pragma unroll
            for (int g = 0; g < 4; g++)
                ldsm4(&wreg[g * 4], swb + 3 * 8192 + (g * 16 + ldrow) * 128 + kb);
#pragma unroll
            for (int nt = 0; nt < 8; nt++) {
                mma16816(acc[nt], Ph, &wreg[nt * 2]);
                mma16816(acc[nt], Pm, &wreg[nt * 2]);
                mma16816(acc[nt], Pl, &wreg[nt * 2]);
            }
#pragma unroll
            for (int g = 0; g < 4; g++)
                ldsm4(&wreg[g * 4], swb + 4 * 8192 + (g * 16 + ldrow) * 128 + kb);
#pragma unroll
            for (int nt = 0; nt < 8; nt++) {
                mma16816(acc[nt], Ph, &wreg[nt * 2]);
                mma16816(acc[nt], Pm, &wreg[nt * 2]);
            }
#pragma unroll
            for (int g = 0; g < 4; g++)
                ldsm4(&wreg[g * 4], swb + 5 * 8192 + (g * 16 + ldrow) * 128 + kb);
#pragma unroll
            for (int nt = 0; nt < 8; nt++)
                mma16816(acc[nt], Ph, &wreg[nt * 2]);
        }
    }

    // ---- epilogue: store acc frags to partials
    float* dst0 = g_part + ((size_t)ks * TOK + rA) * NE;
    float* dst1 = dst0 + (size_t)8 * NE;
#pragma unroll
    for (int nt = 0; nt < 8; nt++) {
        *(float2*)&dst0[nt * 8 + qc] = make_float2(acc[nt][0], acc[nt][1]);
        *(float2*)&dst1[nt * 8 + qc] = make_float2(acc[nt][2], acc[nt][3]);
    }
}

// ---------------- reduce + top-2 + renormalized softmax ----------------
__global__ __launch_bounds__(256)
void topk_kernel(const float* __restrict__ bvec, float* __restrict__ out) {
    const int gtid = blockIdx.x * blockDim.x + threadIdx.x;
    const int tok  = gtid >> 5;
    const int lane = threadIdx.x & 31;
    if (tok >= TOK) return;

    float s0 = 0.0f, s1 = 0.0f;
#pragma unroll
    for (int ks = 0; ks < KSPL; ks++) {
        const float2 v = *(const float2*)&g_part[((size_t)ks * TOK + tok) * NE + lane * 2];
        s0 += v.x; s1 += v.y;
    }
    s0 += bvec[2 * lane];
    s1 += bvec[2 * lane + 1];

    // top-1, jax tie-break (lower index wins on equal)
    float bv; int bi;
    if (s1 > s0) { bv = s1; bi = 2 * lane + 1; } else { bv = s0; bi = 2 * lane; }
#pragma unroll
    for (int off = 16; off > 0; off >>= 1) {
        const float ov = __shfl_down_sync(0xffffffffu, bv, off);
        const int   oi = __shfl_down_sync(0xffffffffu, bi, off);
        if (ov > bv || (ov == bv && oi < bi)) { bv = ov; bi = oi; }
    }
    bv = __shfl_sync(0xffffffffu, bv, 0);
    bi = __shfl_sync(0xffffffffu, bi, 0);

    const float NEG = -3.4e38f;
    float t0 = (2 * lane     == bi) ? NEG : s0;
    float t1 = (2 * lane + 1 == bi) ? NEG : s1;
    float cv; int ci;
    if (t1 > t0) { cv = t1; ci = 2 * lane + 1; } else { cv = t0; ci = 2 * lane; }
#pragma unroll
    for (int off = 16; off > 0; off >>= 1) {
        const float ov = __shfl_down_sync(0xffffffffu, cv, off);
        const int   oi = __shfl_down_sync(0xffffffffu, ci, off);
        if (ov > cv || (ov == cv && oi < ci)) { cv = ov; ci = oi; }
    }

    if (lane == 0) {
        // renormalized top-2 softmax: global denominator cancels, max = bv
        const float r  = expf(cv - bv);
        const float dn = 1.0f + r;
        out[tok * 2]             = 1.0f / dn;
        out[tok * 2 + 1]         = r / dn;
        out[NPROB + tok * 2]     = (float)bi;
        out[NPROB + tok * 2 + 1] = (float)ci;
    }
}

extern "C" void kernel_launch(void* const* d_in, const int* in_sizes, int n_in,
                              void* d_out, int out_size) {
    const float* xr = (const float*)d_in[0];   // x_real [4,2048,2048]
    const float* xi = (const float*)d_in[1];   // x_imag [4,2048,2048]
    const float* W  = (const float*)d_in[2];   // [4096, 64]
    const float* b  = (const float*)d_in[3];   // [64]
    float* out = (float*)d_out;                // [16384 probs][16384 indices]

    wsplit_kernel<<<2 * DD / 64, 256>>>(W);
    dim3 grid(TOK / BM, KSPL);
    gemm_mma_kernel<<<grid, 256>>>(xr, xi);
    topk_kernel<<<TOK * 32 / 256, 256>>>(b, out);
}

// round 9
// speedup vs baseline: 1.4760x; 1.3347x over previous
#include <cuda_runtime.h>
#include <cuda_fp16.h>
#include <math.h>
#include <stdint.h>

// ---------------- problem constants ----------------
#define TOK    8192
#define DD     2048
#define NE     64
#define KSPL   4          // K-split -> grid (64, 4)
#define DSPL   512        // d per split
#define BM     128        // tokens per CTA
#define CHUNK  64         // k per chunk
#define NCHK   (DSPL / CHUNK)   // 8 chunks
#define NPROB  16384
#define LSCALE 2048.0f    // 2^11 residual scale
#define LINV   (1.0f / 2048.0f)

// partial scores [KSPL][TOK][NE] = 8 MB
__device__ float g_part[KSPL * TOK * NE];
// W transposed + 2-level fp16 split (l pre-scaled by 2^11): [expert n][feature k]
__device__ __half g_Wh[NE * 2 * DD];
__device__ __half g_Wl[NE * 2 * DD];

// ---------------- helpers ----------------
__device__ __forceinline__ uint32_t smem_u32(const void* p) {
    uint32_t a;
    asm("{ .reg .u64 t; cvta.to.shared.u64 t, %1; cvt.u32.u64 %0, t; }" : "=r"(a) : "l"(p));
    return a;
}
__device__ __forceinline__ uint32_t packh2(__half x, __half y) {
    __half2 v = __halves2half2(x, y);
    return *reinterpret_cast<uint32_t*>(&v);
}
// 2-level fp16 split of a float pair; l scaled by 2^11
__device__ __forceinline__ void split2h(float x, float y, uint32_t& h, uint32_t& l) {
    const __half hx = __float2half_rn(x);
    const __half hy = __float2half_rn(y);
    const float rx = (x - __half2float(hx)) * LSCALE;
    const float ry = (y - __half2float(hy)) * LSCALE;
    h = packh2(hx, hy);
    l = packh2(__float2half_rn(rx), __float2half_rn(ry));
}
__device__ __forceinline__ void mma16816(float* c, const uint32_t* a, const uint32_t* b) {
    asm volatile(
        "mma.sync.aligned.m16n8k16.row.col.f32.f16.f16.f32 "
        "{%0,%1,%2,%3}, {%4,%5,%6,%7}, {%8,%9}, {%0,%1,%2,%3};"
        : "+f"(c[0]), "+f"(c[1]), "+f"(c[2]), "+f"(c[3])
        : "r"(a[0]), "r"(a[1]), "r"(a[2]), "r"(a[3]), "r"(b[0]), "r"(b[1]));
}
__device__ __forceinline__ void ldsm4(uint32_t* r, uint32_t addr) {
    asm volatile("ldmatrix.sync.aligned.m8n8.x4.shared.b16 {%0,%1,%2,%3}, [%4];"
                 : "=r"(r[0]), "=r"(r[1]), "=r"(r[2]), "=r"(r[3]) : "r"(addr));
}
__device__ __forceinline__ void stsh128(uint32_t addr, uint4 v) {
    asm volatile("st.shared.v4.b32 [%0], {%1, %2, %3, %4};"
                 :: "r"(addr), "r"(v.x), "r"(v.y), "r"(v.z), "r"(v.w) : "memory");
}

// ---------------- setup: transpose + 2-level fp16-split W ----------------
__global__ __launch_bounds__(256)
void wsplit_kernel(const float* __restrict__ W) {
    __shared__ float tile[64][65];
    const int k0  = blockIdx.x * 64;
    const int tid = threadIdx.x;
    for (int i = tid; i < 64 * 64; i += 256) {
        const int r = i >> 6, n = i & 63;
        tile[r][n] = W[(size_t)(k0 + r) * NE + n];
    }
    __syncthreads();
    const int n  = tid >> 2;
    const int kb = (tid & 3) * 16;
    union { __half h[16]; uint4 q[2]; } hb, lb;
#pragma unroll
    for (int kk = 0; kk < 16; kk++) {
        const float v = tile[kb + kk][n];
        const __half h = __float2half_rn(v);
        const float r1 = (v - __half2float(h)) * LSCALE;
        hb.h[kk] = h;
        lb.h[kk] = __float2half_rn(r1);
    }
    const size_t idx = (size_t)n * (2 * DD) + k0 + kb;
    *(uint4*)(g_Wh + idx)     = hb.q[0];
    *(uint4*)(g_Wh + idx + 8) = hb.q[1];
    *(uint4*)(g_Wl + idx)     = lb.q[0];
    *(uint4*)(g_Wl + idx + 8) = lb.q[1];
}

// ---------------- main: fused amp/phase + 2-level fp16 split mma GEMM ----------------
// 8 warps, each owns m16 (16 tokens) x n64. A frags built in registers.
// acc_main: h*h products; acc_corr: h*l' + l'*h (combined epilogue: main + corr/2048)
__global__ __launch_bounds__(256, 2)
void gemm_mma_kernel(const float* __restrict__ xr, const float* __restrict__ xi) {
    // W tiles: 4 arrays [Wa_h, Wa_l, Wp_h, Wp_l], 64n x 64k fp16, swizzled
    __shared__ __align__(128) uint8_t sW[4 * 8192];
    const uint32_t swb = smem_u32(sW);

    const int tid  = threadIdx.x;
    const int w    = tid >> 5;
    const int lane = tid & 31;
    const int qr   = lane >> 2;          // frag row 0..7
    const int qc   = (lane & 3) * 2;     // frag col pair
    const int tok0 = blockIdx.x * BM;
    const int ks   = blockIdx.y;

    // ldmatrix lane-address constants
    const uint32_t ldrow = ((lane >> 4) << 3) + (lane & 7);     // 0..15
    const uint32_t kboff = ((lane >> 3) & 1) * 16;              // 0 / 16 bytes
    const uint32_t kxor  = (lane & 7) << 4;                     // swizzle XOR

    float accm[8][4], accc[8][4];
#pragma unroll
    for (int nt = 0; nt < 8; nt++)
#pragma unroll
        for (int j = 0; j < 4; j++) { accm[nt][j] = 0.0f; accc[nt][j] = 0.0f; }

    const int rA = tok0 + w * 16 + qr;         // token row (and +8)

    for (int c = 0; c < NCHK; c++) {
        const int koff = ks * DSPL + c * CHUNK;
        __syncthreads();
        // ---- stage W: 4 arrays, each thread moves 32B per array (swizzled smem)
        {
            const int n  = tid >> 2;
            const int ke = (tid & 3) * 16;
            const size_t gA = (size_t)n * (2 * DD) + koff + ke;
            const size_t gP = gA + DD;
            const uint32_t row = (uint32_t)n * 128;
            const uint32_t xv  = (uint32_t)(n & 7) << 4;
            const uint32_t c0  = row + (((uint32_t)(ke * 2)) ^ xv);
            const uint32_t c1  = row + (((uint32_t)(ke * 2 + 16)) ^ xv);
            uint4 v;
            v = *(const uint4*)(g_Wh + gA);     stsh128(swb + 0 * 8192 + c0, v);
            v = *(const uint4*)(g_Wh + gA + 8); stsh128(swb + 0 * 8192 + c1, v);
            v = *(const uint4*)(g_Wl + gA);     stsh128(swb + 1 * 8192 + c0, v);
            v = *(const uint4*)(g_Wl + gA + 8); stsh128(swb + 1 * 8192 + c1, v);
            v = *(const uint4*)(g_Wh + gP);     stsh128(swb + 2 * 8192 + c0, v);
            v = *(const uint4*)(g_Wh + gP + 8); stsh128(swb + 2 * 8192 + c1, v);
            v = *(const uint4*)(g_Wl + gP);     stsh128(swb + 3 * 8192 + c0, v);
            v = *(const uint4*)(g_Wl + gP + 8); stsh128(swb + 3 * 8192 + c1, v);
        }
        __syncthreads();

#pragma unroll
        for (int kt = 0; kt < 4; kt++) {
            const int cc = kt * 16 + qc;     // chunk-local col (even)
            // ---- load x for this thread's A-fragment positions
            const size_t b0 = (size_t)rA * DD + koff + cc;
            const size_t b1 = b0 + (size_t)8 * DD;
            const float2 r00 = *(const float2*)(xr + b0);
            const float2 r02 = *(const float2*)(xr + b0 + 8);
            const float2 r10 = *(const float2*)(xr + b1);
            const float2 r12 = *(const float2*)(xr + b1 + 8);
            const float2 i00 = *(const float2*)(xi + b0);
            const float2 i02 = *(const float2*)(xi + b0 + 8);
            const float2 i10 = *(const float2*)(xi + b1);
            const float2 i12 = *(const float2*)(xi + b1 + 8);

            // ---- amp / phase (8 elems)
            const float a00 = sqrtf(fmaf(r00.x, r00.x, i00.x * i00.x)), p00 = atan2f(i00.x, r00.x);
            const float a01 = sqrtf(fmaf(r00.y, r00.y, i00.y * i00.y)), p01 = atan2f(i00.y, r00.y);
            const float a10 = sqrtf(fmaf(r10.x, r10.x, i10.x * i10.x)), p10 = atan2f(i10.x, r10.x);
            const float a11 = sqrtf(fmaf(r10.y, r10.y, i10.y * i10.y)), p11 = atan2f(i10.y, r10.y);
            const float a02 = sqrtf(fmaf(r02.x, r02.x, i02.x * i02.x)), p02 = atan2f(i02.x, r02.x);
            const float a03 = sqrtf(fmaf(r02.y, r02.y, i02.y * i02.y)), p03 = atan2f(i02.y, r02.y);
            const float a12 = sqrtf(fmaf(r12.x, r12.x, i12.x * i12.x)), p12 = atan2f(i12.x, r12.x);
            const float a13 = sqrtf(fmaf(r12.y, r12.y, i12.y * i12.y)), p13 = atan2f(i12.y, r12.y);

            // ---- 2-level fp16 split into A-fragment layout (l scaled 2^11)
            uint32_t Ah[4], Al[4], Ph[4], Pl[4];
            split2h(a00, a01, Ah[0], Al[0]);
            split2h(a10, a11, Ah[1], Al[1]);
            split2h(a02, a03, Ah[2], Al[2]);
            split2h(a12, a13, Ah[3], Al[3]);
            split2h(p00, p01, Ph[0], Pl[0]);
            split2h(p10, p11, Ph[1], Pl[1]);
            split2h(p02, p03, Ph[2], Pl[2]);
            split2h(p12, p13, Ph[3], Pl[3]);

            const uint32_t kb = ((uint32_t)(kt * 32) + kboff) ^ kxor;
            uint32_t wreg[16];

            // ---- amp Wh: main Ah*Wh, corr Al'*Wh
#pragma unroll
            for (int g = 0; g < 4; g++)
                ldsm4(&wreg[g * 4], swb + 0 * 8192 + (g * 16 + ldrow) * 128 + kb);
#pragma unroll
            for (int nt = 0; nt < 8; nt++) {
                mma16816(accm[nt], Ah, &wreg[nt * 2]);
                mma16816(accc[nt], Al, &wreg[nt * 2]);
            }
            // ---- amp Wl': corr Ah*Wl'
#pragma unroll
            for (int g = 0; g < 4; g++)
                ldsm4(&wreg[g * 4], swb + 1 * 8192 + (g * 16 + ldrow) * 128 + kb);
#pragma unroll
            for (int nt = 0; nt < 8; nt++)
                mma16816(accc[nt], Ah, &wreg[nt * 2]);

            // ---- phase Wh: main Ph*Wh, corr Pl'*Wh
#pragma unroll
            for (int g = 0; g < 4; g++)
                ldsm4(&wreg[g * 4], swb + 2 * 8192 + (g * 16 + ldrow) * 128 + kb);
#pragma unroll
            for (int nt = 0; nt < 8; nt++) {
                mma16816(accm[nt], Ph, &wreg[nt * 2]);
                mma16816(accc[nt], Pl, &wreg[nt * 2]);
            }
            // ---- phase Wl': corr Ph*Wl'
#pragma unroll
            for (int g = 0; g < 4; g++)
                ldsm4(&wreg[g * 4], swb + 3 * 8192 + (g * 16 + ldrow) * 128 + kb);
#pragma unroll
            for (int nt = 0; nt < 8; nt++)
                mma16816(accc[nt], Ph, &wreg[nt * 2]);
        }
    }

    // ---- epilogue: combine main + corr/2048, store to partials
    float* dst0 = g_part + ((size_t)ks * TOK + rA) * NE;
    float* dst1 = dst0 + (size_t)8 * NE;
#pragma unroll
    for (int nt = 0; nt < 8; nt++) {
        const float v0 = fmaf(accc[nt][0], LINV, accm[nt][0]);
        const float v1 = fmaf(accc[nt][1], LINV, accm[nt][1]);
        const float v2 = fmaf(accc[nt][2], LINV, accm[nt][2]);
        const float v3 = fmaf(accc[nt][3], LINV, accm[nt][3]);
        *(float2*)&dst0[nt * 8 + qc] = make_float2(v0, v1);
        *(float2*)&dst1[nt * 8 + qc] = make_float2(v2, v3);
    }
}

// ---------------- reduce + top-2 + renormalized softmax ----------------
__global__ __launch_bounds__(256)
void topk_kernel(const float* __restrict__ bvec, float* __restrict__ out) {
    const int gtid = blockIdx.x * blockDim.x + threadIdx.x;
    const int tok  = gtid >> 5;
    const int lane = threadIdx.x & 31;
    if (tok >= TOK) return;

    float s0 = 0.0f, s1 = 0.0f;
#pragma unroll
    for (int ks = 0; ks < KSPL; ks++) {
        const float2 v = *(const float2*)&g_part[((size_t)ks * TOK + tok) * NE + lane * 2];
        s0 += v.x; s1 += v.y;
    }
    s0 += bvec[2 * lane];
    s1 += bvec[2 * lane + 1];

    // top-1, jax tie-break (lower index wins on equal)
    float bv; int bi;
    if (s1 > s0) { bv = s1; bi = 2 * lane + 1; } else { bv = s0; bi = 2 * lane; }
#pragma unroll
    for (int off = 16; off > 0; off >>= 1) {
        const float ov = __shfl_down_sync(0xffffffffu, bv, off);
        const int   oi = __shfl_down_sync(0xffffffffu, bi, off);
        if (ov > bv || (ov == bv && oi < bi)) { bv = ov; bi = oi; }
    }
    bv = __shfl_sync(0xffffffffu, bv, 0);
    bi = __shfl_sync(0xffffffffu, bi, 0);

    const float NEG = -3.4e38f;
    float t0 = (2 * lane     == bi) ? NEG : s0;
    float t1 = (2 * lane + 1 == bi) ? NEG : s1;
    float cv; int ci;
    if (t1 > t0) { cv = t1; ci = 2 * lane + 1; } else { cv = t0; ci = 2 * lane; }
#pragma unroll
    for (int off = 16; off > 0; off >>= 1) {
        const float ov = __shfl_down_sync(0xffffffffu, cv, off);
        const int   oi = __shfl_down_sync(0xffffffffu, ci, off);
        if (ov > cv || (ov == cv && oi < ci)) { cv = ov; ci = oi; }
    }

    if (lane == 0) {
        // renormalized top-2 softmax: global denominator cancels, max = bv
        const float r  = expf(cv - bv);
        const float dn = 1.0f + r;
        out[tok * 2]             = 1.0f / dn;
        out[tok * 2 + 1]         = r / dn;
        out[NPROB + tok * 2]     = (float)bi;
        out[NPROB + tok * 2 + 1] = (float)ci;
    }
}

extern "C" void kernel_launch(void* const* d_in, const int* in_sizes, int n_in,
                              void* d_out, int out_size) {
    const float* xr = (const float*)d_in[0];   // x_real [4,2048,2048]
    const float* xi = (const float*)d_in[1];   // x_imag [4,2048,2048]
    const float* W  = (const float*)d_in[2];   // [4096, 64]
    const float* b  = (const float*)d_in[3];   // [64]
    float* out = (float*)d_out;                // [16384 probs][16384 indices]

    wsplit_kernel<<<2 * DD / 64, 256>>>(W);
    dim3 grid(TOK / BM, KSPL);
    gemm_mma_kernel<<<grid, 256>>>(xr, xi);
    topk_kernel<<<TOK * 32 / 256, 256>>>(b, out);
}